// round 14
// baseline (speedup 1.0000x reference)
#include <cuda_runtime.h>
#include <cuda_bf16.h>
#include <cuda_fp8.h>
#include <math.h>
#include <stdint.h>

#define BATCH 4
#define TLEN  4096
#define DIM   768
#define NSEL  256
#define HID   200
#define MTILE 64             // pairs per CTA (8x8 token block)
#define NB8   32
#define NBLK  528            // NB8*(NB8+1)/2
#define K2PAD 256
#define L1C   (DIM / 64)     // 12 chunks of 64 fp8
#define L2C   4              // 256/64
#define NTILES 25
#define XR    784            // X row stride bytes (768 + 16 pad)
#define HS_STRIDE 240        // Hs row stride bytes

// dynamic smem layout (bytes)
#define X_OFF   0                      // 64*784 = 50176
#define HS_OFF  50176                  // 64*240 = 15360
#define DYN_BYTES 65536
#define ES_OFF  HS_OFF                 // E fp32 staging overlays Hs region? 16*384*4=24576 > 15360!
// E staging needs 24576B; overlay X region instead is impossible (X being built).
// Stage E in halves of 192 cols: 16*192*4 = 12288 <= 15360. 4 quarter-passes.

#define W_SCALE   32.0f
#define H_SCALE   8.0f
#define INV_W     (1.0f / 32.0f)
#define INV_HW    (1.0f / 256.0f)

// ---------------- device scratch ----------------
__device__ float    g_E  [BATCH * NSEL * DIM];
__device__ float    g_AB [BATCH * NSEL * 2 * HID];
__device__ uint8_t  g_W1q[HID * DIM];               // e4m3 of 32*W1c^T [h][d]
__device__ uint8_t  g_W2q[HID * K2PAD];             // e4m3 of 32*W2^T  [h][k]
__device__ float    g_S  [BATCH * NSEL * NSEL];

// ---------------- helpers ----------------
__device__ __forceinline__ void mma_fp8(float* c, const uint32_t* a, const uint32_t* b) {
    asm volatile(
        "mma.sync.aligned.m16n8k32.row.col.f32.e4m3.e4m3.f32 "
        "{%0,%1,%2,%3}, {%4,%5,%6,%7}, {%8,%9}, {%0,%1,%2,%3};"
        : "+f"(c[0]), "+f"(c[1]), "+f"(c[2]), "+f"(c[3])
        : "r"(a[0]), "r"(a[1]), "r"(a[2]), "r"(a[3]), "r"(b[0]), "r"(b[1]));
}
__device__ __forceinline__ void ldsm_x4(uint32_t* r, uint32_t addr) {
    asm volatile("ldmatrix.sync.aligned.m8n8.x4.shared.b16 {%0,%1,%2,%3}, [%4];"
                 : "=r"(r[0]), "=r"(r[1]), "=r"(r[2]), "=r"(r[3]) : "r"(addr));
}
__device__ __forceinline__ void cpasync16(uint32_t smem_addr, const void* gsrc) {
    asm volatile("cp.async.cg.shared.global [%0], [%1], 16;"
                 :: "r"(smem_addr), "l"(gsrc) : "memory");
}
__device__ __forceinline__ void cpasync_commit() {
    asm volatile("cp.async.commit_group;" ::: "memory");
}
__device__ __forceinline__ void cpasync_wait0() {
    asm volatile("cp.async.wait_group 0;" ::: "memory");
}
__device__ __forceinline__ uint32_t pack_e4m3_4(float a0, float a1, float a2, float a3) {
    uint16_t lo, hi;
    asm("cvt.rn.satfinite.e4m3x2.f32 %0, %1, %2;" : "=h"(lo) : "f"(a1), "f"(a0));
    asm("cvt.rn.satfinite.e4m3x2.f32 %0, %1, %2;" : "=h"(hi) : "f"(a3), "f"(a2));
    return (uint32_t)lo | ((uint32_t)hi << 16);
}
__device__ __forceinline__ uint16_t pack_e4m3_2(float a0, float a1) {
    uint16_t v;
    asm("cvt.rn.satfinite.e4m3x2.f32 %0, %1, %2;" : "=h"(v) : "f"(a1), "f"(a0));
    return v;
}

// ---------------- fused prep: gather + W1q + W2q ----------------
#define PREP_GATH  (BATCH * NSEL)                       // 1024
#define PREP_W1    ((HID * DIM + 255) / 256)            // 600
#define PREP_W2    ((HID * K2PAD + 255) / 256)          // 200
#define PREP_BLKS  (PREP_GATH + PREP_W1 + PREP_W2)

__global__ void k_prep(const float* __restrict__ emb, const int* __restrict__ idx,
                       const float* __restrict__ W1, const float* __restrict__ W2) {
    int blk = blockIdx.x;
    int tid = threadIdx.x;
    if (blk < PREP_GATH) {
        int b = blk / NSEL, n = blk % NSEL;
        int t = idx[b * NSEL + n];
        const float4* src = (const float4*)(emb + ((size_t)b * TLEN + t) * DIM);
        float4* dst = (float4*)(g_E + (size_t)blk * DIM);
        if (tid < DIM / 4) dst[tid] = src[tid];
        return;
    }
    blk -= PREP_GATH;
    if (blk < PREP_W1) {
        int e = blk * 256 + tid;
        if (e < HID * DIM) {
            int h = e / DIM, d = e % DIM;
            float v = W_SCALE * W1[(size_t)(2 * DIM + d) * HID + h];
            g_W1q[e] = (uint8_t)__nv_cvt_float_to_fp8(v, __NV_SATFINITE, __NV_E4M3);
        }
        return;
    }
    blk -= PREP_W1;
    {
        int e = blk * 256 + tid;
        if (e < HID * K2PAD) {
            int h = e / K2PAD, k = e % K2PAD;
            float v = (k < HID) ? W_SCALE * W2[(size_t)k * HID + h] : 0.f;
            g_W2q[e] = (uint8_t)__nv_cvt_float_to_fp8(v, __NV_SATFINITE, __NV_E4M3);
        }
    }
}

// ---------------- exact A/B partials (fp32 SIMT, small) ----------------
__global__ void k_ab(const float* __restrict__ W1) {
    __shared__ __align__(16) float As[16][64 + 4];
    __shared__ __align__(16) float Bs[16][64 + 4];
    int bm = blockIdx.x * 64, bn = blockIdx.y * 64;
    int tx = threadIdx.x % 16, ty = threadIdx.x / 16;
    float acc[4][4] = {};
    for (int k0 = 0; k0 < DIM; k0 += 16) {
        for (int t = threadIdx.x; t < 1024; t += 256) {
            int k = t % 16, m = t / 16;
            As[k][m] = g_E[(size_t)(bm + m) * DIM + k0 + k];
        }
        for (int t = threadIdx.x; t < 1024; t += 256) {
            int n = t % 64, k = t / 64;
            int c = bn + n;
            float v = 0.f;
            if (c < 2 * HID) {
                int half = c / HID, h = c - half * HID;
                v = W1[(size_t)(half * DIM + k0 + k) * HID + h];
            }
            Bs[k][n] = v;
        }
        __syncthreads();
        #pragma unroll
        for (int k = 0; k < 16; ++k) {
            float a[4], bb[4];
            #pragma unroll
            for (int u = 0; u < 4; ++u) a[u] = As[k][ty * 4 + u];
            #pragma unroll
            for (int v = 0; v < 4; ++v) bb[v] = Bs[k][tx * 4 + v];
            #pragma unroll
            for (int u = 0; u < 4; ++u)
                #pragma unroll
                for (int v = 0; v < 4; ++v)
                    acc[u][v] = fmaf(a[u], bb[v], acc[u][v]);
        }
        __syncthreads();
    }
    #pragma unroll
    for (int u = 0; u < 4; ++u)
        #pragma unroll
        for (int v = 0; v < 4; ++v) {
            int c = bn + tx * 4 + v;
            if (c < 2 * HID)
                g_AB[(size_t)(bm + ty * 4 + u) * (2 * HID) + c] = acc[u][v];
        }
}

// ================= fused MLP: X resident, W via direct LDG (syncless mainloops) =================
__global__ __launch_bounds__(256, 2)
void k_fused(const float* __restrict__ b1, const float* __restrict__ b2,
             const float* __restrict__ W3, const float* __restrict__ b3) {
    extern __shared__ __align__(16) char dynsm[];
    uint32_t dynbase = (uint32_t)__cvta_generic_to_shared(dynsm);
    uint32_t x_base = dynbase + X_OFF;
    uint32_t hs_base = dynbase + HS_OFF;
    uint32_t es_base = dynbase + ES_OFF;
    uint8_t* Xs = (uint8_t*)(dynsm + X_OFF);
    float*   Es = (float*)(dynsm + ES_OFF);     // [16][192] fp32 staging (overlays Hs)
    uint8_t* Hs = (uint8_t*)(dynsm + HS_OFF);

    __shared__ float b1s[HID], b2s[HID], W3s[HID];
    __shared__ float sred[MTILE][4];

    int tid = threadIdx.x;
    int b = blockIdx.y;

    // decode token block (bi, bj), bi >= bj
    int tb = blockIdx.x;
    int bi = (int)((sqrtf(8.0f * (float)tb + 1.0f) - 1.0f) * 0.5f);
    while (bi * (bi + 1) / 2 > tb) --bi;
    while ((bi + 1) * (bi + 2) / 2 <= tb) ++bi;
    int bj = tb - bi * (bi + 1) / 2;

    if (tid < HID) { b1s[tid] = b1[tid]; b2s[tid] = b2[tid]; W3s[tid] = W3[tid]; }

    const float* Eb = g_E + (size_t)b * NSEL * DIM;
    int wid = tid / 32, lane = tid % 32;
    int wm = wid & 1, wn = wid >> 1;
    int q = lane >> 2, l4 = lane & 3;

    int rowA = wm * 32 + (lane & 15);          // + mt*16
    int colA = (lane >> 4) * 16;

    // ---------------- prologue: build full X in 4 quarter-passes of 192 cols ----------------
    #pragma unroll
    for (int hq = 0; hq < 4; ++hq) {
        int hc = hq * 192;
        // stage E fp32: 16 rows x 192 floats = 768 segs of 16B
        #pragma unroll
        for (int u = 0; u < 3; ++u) {
            int seg = tid + u * 256;
            int row = seg / 48, sc = seg % 48;
            int tok = (row < 8) ? (bi * 8 + row) : (bj * 8 + row - 8);
            cpasync16(es_base + row * 768 + sc * 16,
                      Eb + (size_t)tok * DIM + hc + sc * 4);
        }
        cpasync_commit();
        cpasync_wait0();
        __syncthreads();
        // build X cols [hc, hc+192): 3072 packs
        #pragma unroll
        for (int u = 0; u < 12; ++u) {
            int e = tid + u * 256;
            int row = e / 48, pc = e % 48;
            int ri = row >> 3, rj = row & 7;
            const float4 xi = *(const float4*)&Es[ri * 192 + pc * 4];
            const float4 xj = *(const float4*)&Es[(8 + rj) * 192 + pc * 4];
            *(uint32_t*)&Xs[row * XR + hc + pc * 4] =
                pack_e4m3_4(xi.x * xj.x, xi.y * xj.y, xi.z * xj.z, xi.w * xj.w);
        }
        __syncthreads();
    }

    float acc[2][7][4];
    #pragma unroll
    for (int mt = 0; mt < 2; ++mt)
        #pragma unroll
        for (int t = 0; t < 7; ++t)
            #pragma unroll
            for (int v = 0; v < 4; ++v) acc[mt][t][v] = 0.f;

    // ---------------- layer-1 mainloop: SYNCLESS. B frags via LDG from L2-hot W1 ----------------
    // reg m of B frag = W1q[n = nt_g*8+q][c*64 + m*16 + l4*4] (matches ldmatrix layout).
    {
        const uint8_t* Wrow[7];
        #pragma unroll
        for (int t = 0; t < 7; ++t) {
            int nt_g = wn + 4 * t;
            Wrow[t] = g_W1q + (size_t)(nt_g * 8 + q) * DIM + l4 * 4;
        }
        for (int c = 0; c < L1C; ++c) {
            uint32_t a[2][2][4];
            #pragma unroll
            for (int ks = 0; ks < 2; ++ks)
                #pragma unroll
                for (int mt = 0; mt < 2; ++mt)
                    ldsm_x4(a[ks][mt],
                            x_base + (rowA + mt * 16) * XR + c * 64 + ks * 32 + colA);
            #pragma unroll
            for (int t = 0; t < 7; ++t) {
                int nt_g = wn + 4 * t;
                if (nt_g < NTILES) {
                    uint32_t bb[4];
                    #pragma unroll
                    for (int m = 0; m < 4; ++m)
                        bb[m] = *(const uint32_t*)(Wrow[t] + c * 64 + m * 16);
                    #pragma unroll
                    for (int ks = 0; ks < 2; ++ks)
                        #pragma unroll
                        for (int mt = 0; mt < 2; ++mt)
                            mma_fp8(acc[mt][t], a[ks][mt], bb + ks * 2);
                }
            }
        }
    }

    __syncthreads();    // X no longer needed; Hs region about to be written (overlaid Es is dead)

    // ---------------- layer-1 epilogue -> Hs (e4m3 x8); AB from global ----------------
    {
        const float* ABb = g_AB + (size_t)b * NSEL * (2 * HID);
        #pragma unroll
        for (int mt = 0; mt < 2; ++mt) {
            #pragma unroll
            for (int half = 0; half < 2; ++half) {
                int r = wm * 32 + mt * 16 + q + 8 * half;
                int ri = r >> 3, rj = r & 7;
                const float* Ai = ABb + (size_t)(bi * 8 + ri) * (2 * HID);
                const float* Bj = ABb + (size_t)(bj * 8 + rj) * (2 * HID) + HID;
                #pragma unroll
                for (int t = 0; t < 7; ++t) {
                    int nt_g = wn + 4 * t;
                    if (nt_g < NTILES) {
                        int col = nt_g * 8 + 2 * l4;
                        float2 ai = *(const float2*)(Ai + col);
                        float2 bj2 = *(const float2*)(Bj + col);
                        float v0 = acc[mt][t][half * 2 + 0] * INV_W + ai.x + bj2.x + b1s[col];
                        float v1 = acc[mt][t][half * 2 + 1] * INV_W + ai.y + bj2.y + b1s[col + 1];
                        uint16_t p = pack_e4m3_2(H_SCALE * fmaxf(v0, 0.f),
                                                 H_SCALE * fmaxf(v1, 0.f));
                        *(uint16_t*)(Hs + r * HS_STRIDE + col) = p;
                    }
                }
            }
        }
    }
    // zero pad cols [200,240)
    for (int e = tid; e < MTILE * 10; e += 256) {
        int r = e / 10, cc = HID + (e % 10) * 4;
        *(uint32_t*)(Hs + r * HS_STRIDE + cc) = 0u;
    }

    #pragma unroll
    for (int mt = 0; mt < 2; ++mt)
        #pragma unroll
        for (int t = 0; t < 7; ++t)
            #pragma unroll
            for (int v = 0; v < 4; ++v) acc[mt][t][v] = 0.f;

    __syncthreads();    // Hs complete before any warp reads it

    // ---------------- layer-2 mainloop: SYNCLESS. A from Hs, B via LDG from W2 ----------------
    {
        const uint8_t* Wrow[7];
        #pragma unroll
        for (int t = 0; t < 7; ++t) {
            int nt_g = wn + 4 * t;
            Wrow[t] = g_W2q + (size_t)(nt_g * 8 + q) * K2PAD + l4 * 4;
        }
        for (int c = 0; c < L2C; ++c) {
            uint32_t a[2][2][4];
            #pragma unroll
            for (int ks = 0; ks < 2; ++ks)
                #pragma unroll
                for (int mt = 0; mt < 2; ++mt)
                    ldsm_x4(a[ks][mt],
                            hs_base + (rowA + mt * 16) * HS_STRIDE + c * 64 + ks * 32 + colA);
            #pragma unroll
            for (int t = 0; t < 7; ++t) {
                int nt_g = wn + 4 * t;
                if (nt_g < NTILES) {
                    uint32_t bb[4];
                    #pragma unroll
                    for (int m = 0; m < 4; ++m)
                        bb[m] = *(const uint32_t*)(Wrow[t] + c * 64 + m * 16);
                    #pragma unroll
                    for (int ks = 0; ks < 2; ++ks)
                        #pragma unroll
                        for (int mt = 0; mt < 2; ++mt)
                            mma_fp8(acc[mt][t], a[ks][mt], bb + ks * 2);
                }
            }
        }
    }

    // ---------------- scoring epilogue ----------------
    #pragma unroll
    for (int mt = 0; mt < 2; ++mt) {
        #pragma unroll
        for (int half = 0; half < 2; ++half) {
            float sp = 0.f;
            #pragma unroll
            for (int t = 0; t < 7; ++t) {
                int nt_g = wn + 4 * t;
                if (nt_g < NTILES) {
                    int col = nt_g * 8 + 2 * l4;
                    float h0 = fmaxf(acc[mt][t][half * 2 + 0] * INV_HW + b2s[col], 0.f);
                    float h1 = fmaxf(acc[mt][t][half * 2 + 1] * INV_HW + b2s[col + 1], 0.f);
                    sp = fmaf(h0, W3s[col], sp);
                    sp = fmaf(h1, W3s[col + 1], sp);
                }
            }
            sp += __shfl_xor_sync(0xFFFFFFFFu, sp, 1);
            sp += __shfl_xor_sync(0xFFFFFFFFu, sp, 2);
            if (l4 == 0) {
                int r = wm * 32 + mt * 16 + q + 8 * half;
                sred[r][wn] = sp;
            }
        }
    }
    __syncthreads();
    if (tid < MTILE) {
        float s = sred[tid][0] + sred[tid][1] + sred[tid][2] + sred[tid][3] + b3[0];
        int i = bi * 8 + (tid >> 3), j = bj * 8 + (tid & 7);
        if (i > j)
            g_S[((size_t)b * NSEL + i) * NSEL + j] = s;
    }
}

// ---------------- row softmax + fill ----------------
__global__ void k_soft(float* __restrict__ out) {
    int bn = blockIdx.x;
    int i = bn % NSEL;
    const float* Srow = g_S + (size_t)bn * NSEL;
    float* orow = out + (size_t)bn * NSEL;
    __shared__ float red[256];
    int tid = threadIdx.x;

    float mx = -1e30f;
    for (int j = tid; j <= i; j += 256) {
        float l = (j == i) ? 0.f : Srow[j];
        mx = fmaxf(mx, l);
    }
    red[tid] = mx; __syncthreads();
    for (int s = 128; s > 0; s >>= 1) {
        if (tid < s) red[tid] = fmaxf(red[tid], red[tid + s]);
        __syncthreads();
    }
    mx = red[0]; __syncthreads();

    float sum = 0.f;
    for (int j = tid; j <= i; j += 256) {
        float l = (j == i) ? 0.f : Srow[j];
        sum += __expf(l - mx);
    }
    red[tid] = sum; __syncthreads();
    for (int s = 128; s > 0; s >>= 1) {
        if (tid < s) red[tid] += red[tid + s];
        __syncthreads();
    }
    sum = red[0];
    float inv = 1.0f / sum;

    for (int j = tid; j < NSEL; j += 256) {
        if (j <= i) {
            float l = (j == i) ? 0.f : Srow[j];
            orow[j] = __expf(l - mx) * inv;
        } else {
            orow[j] = -1000.0f;
        }
    }
}

// ---------------- launch ----------------
extern "C" void kernel_launch(void* const* d_in, const int* in_sizes, int n_in,
                              void* d_out, int out_size) {
    const float* emb = (const float*)d_in[0];
    const int*   idx = (const int*)  d_in[1];
    const float* W1  = (const float*)d_in[2];
    const float* b1  = (const float*)d_in[3];
    const float* W2  = (const float*)d_in[4];
    const float* b2  = (const float*)d_in[5];
    const float* W3  = (const float*)d_in[6];
    const float* b3  = (const float*)d_in[7];
    float* out = (float*)d_out;

    static int configured = 0;
    if (!configured) {
        cudaFuncSetAttribute(k_fused, cudaFuncAttributeMaxDynamicSharedMemorySize,
                             DYN_BYTES);
        configured = 1;
    }

    k_prep<<<PREP_BLKS, 256>>>(emb, idx, W1, W2);
    k_ab<<<dim3(16, 7), 256>>>(W1);
    k_fused<<<dim3(NBLK, BATCH), 256, DYN_BYTES>>>(b1, b2, W3, b3);
    k_soft<<<BATCH * NSEL, 256>>>(out);
}

// round 15
// speedup vs baseline: 1.3231x; 1.3231x over previous
#include <cuda_runtime.h>
#include <cuda_bf16.h>
#include <cuda_fp8.h>
#include <math.h>
#include <stdint.h>

#define BATCH 4
#define TLEN  4096
#define DIM   768
#define NSEL  256
#define HID   200
#define MTILE 64             // pairs per CTA (8x8 token block)
#define NB8   32
#define NBLK  528            // NB8*(NB8+1)/2
#define K2PAD 256
#define L1C   (DIM / 64)     // 12 chunks of 64 fp8
#define L2C   4              // 256/64
#define NTILES 25
#define XR    784            // X row stride bytes (768 + 16 pad), conflict-free
#define WS_STRIDE 80         // W chunk row stride bytes
#define HS_STRIDE 240        // Hs row stride bytes

// dynamic smem layout (bytes)
#define X_OFF   0                      // 64*784 = 50176
#define WS0_OFF 50176                  // 200*80 = 16000
#define WS1_OFF 66176                  // 16000
#define HS_OFF  82176                  // 64*240 = 15360
#define DYN_BYTES 97536
#define ES_OFF  WS0_OFF                // E fp32 half staging overlays W ring (24576 <= 32000)

#define W_SCALE   32.0f
#define H_SCALE   8.0f
#define INV_W     (1.0f / 32.0f)
#define INV_HW    (1.0f / 256.0f)

// ---------------- device scratch ----------------
__device__ float    g_E  [BATCH * NSEL * DIM];
__device__ float    g_AB [BATCH * NSEL * 2 * HID];
__device__ uint8_t  g_W1q[HID * DIM];               // e4m3 of 32*W1c^T [h][d]
__device__ uint8_t  g_W2q[HID * K2PAD];             // e4m3 of 32*W2^T  [h][k]
__device__ float    g_S  [BATCH * NSEL * NSEL];

// ---------------- helpers ----------------
__device__ __forceinline__ void mma_fp8(float* c, const uint32_t* a, const uint32_t* b) {
    asm volatile(
        "mma.sync.aligned.m16n8k32.row.col.f32.e4m3.e4m3.f32 "
        "{%0,%1,%2,%3}, {%4,%5,%6,%7}, {%8,%9}, {%0,%1,%2,%3};"
        : "+f"(c[0]), "+f"(c[1]), "+f"(c[2]), "+f"(c[3])
        : "r"(a[0]), "r"(a[1]), "r"(a[2]), "r"(a[3]), "r"(b[0]), "r"(b[1]));
}
__device__ __forceinline__ void ldsm_x4(uint32_t* r, uint32_t addr) {
    asm volatile("ldmatrix.sync.aligned.m8n8.x4.shared.b16 {%0,%1,%2,%3}, [%4];"
                 : "=r"(r[0]), "=r"(r[1]), "=r"(r[2]), "=r"(r[3]) : "r"(addr));
}
__device__ __forceinline__ void cpasync16(uint32_t smem_addr, const void* gsrc) {
    asm volatile("cp.async.cg.shared.global [%0], [%1], 16;"
                 :: "r"(smem_addr), "l"(gsrc) : "memory");
}
__device__ __forceinline__ void cpasync_commit() {
    asm volatile("cp.async.commit_group;" ::: "memory");
}
__device__ __forceinline__ void cpasync_wait0() {
    asm volatile("cp.async.wait_group 0;" ::: "memory");
}
__device__ __forceinline__ uint32_t pack_e4m3_4(float a0, float a1, float a2, float a3) {
    uint16_t lo, hi;
    asm("cvt.rn.satfinite.e4m3x2.f32 %0, %1, %2;" : "=h"(lo) : "f"(a1), "f"(a0));
    asm("cvt.rn.satfinite.e4m3x2.f32 %0, %1, %2;" : "=h"(hi) : "f"(a3), "f"(a2));
    return (uint32_t)lo | ((uint32_t)hi << 16);
}
__device__ __forceinline__ uint16_t pack_e4m3_2(float a0, float a1) {
    uint16_t v;
    asm("cvt.rn.satfinite.e4m3x2.f32 %0, %1, %2;" : "=h"(v) : "f"(a1), "f"(a0));
    return v;
}

// ---------------- fused prep: gather + W1q + W2q ----------------
#define PREP_GATH  (BATCH * NSEL)                       // 1024
#define PREP_W1    ((HID * DIM + 255) / 256)            // 600
#define PREP_W2    ((HID * K2PAD + 255) / 256)          // 200
#define PREP_BLKS  (PREP_GATH + PREP_W1 + PREP_W2)

__global__ void k_prep(const float* __restrict__ emb, const int* __restrict__ idx,
                       const float* __restrict__ W1, const float* __restrict__ W2) {
    int blk = blockIdx.x;
    int tid = threadIdx.x;
    if (blk < PREP_GATH) {
        int b = blk / NSEL, n = blk % NSEL;
        int t = idx[b * NSEL + n];
        const float4* src = (const float4*)(emb + ((size_t)b * TLEN + t) * DIM);
        float4* dst = (float4*)(g_E + (size_t)blk * DIM);
        if (tid < DIM / 4) dst[tid] = src[tid];
        return;
    }
    blk -= PREP_GATH;
    if (blk < PREP_W1) {
        int e = blk * 256 + tid;
        if (e < HID * DIM) {
            int h = e / DIM, d = e % DIM;
            float v = W_SCALE * W1[(size_t)(2 * DIM + d) * HID + h];
            g_W1q[e] = (uint8_t)__nv_cvt_float_to_fp8(v, __NV_SATFINITE, __NV_E4M3);
        }
        return;
    }
    blk -= PREP_W1;
    {
        int e = blk * 256 + tid;
        if (e < HID * K2PAD) {
            int h = e / K2PAD, k = e % K2PAD;
            float v = (k < HID) ? W_SCALE * W2[(size_t)k * HID + h] : 0.f;
            g_W2q[e] = (uint8_t)__nv_cvt_float_to_fp8(v, __NV_SATFINITE, __NV_E4M3);
        }
    }
}

// ---------------- exact A/B partials (fp32 SIMT, small) ----------------
__global__ void k_ab(const float* __restrict__ W1) {
    __shared__ __align__(16) float As[16][64 + 4];
    __shared__ __align__(16) float Bs[16][64 + 4];
    int bm = blockIdx.x * 64, bn = blockIdx.y * 64;
    int tx = threadIdx.x % 16, ty = threadIdx.x / 16;
    float acc[4][4] = {};
    for (int k0 = 0; k0 < DIM; k0 += 16) {
        for (int t = threadIdx.x; t < 1024; t += 256) {
            int k = t % 16, m = t / 16;
            As[k][m] = g_E[(size_t)(bm + m) * DIM + k0 + k];
        }
        for (int t = threadIdx.x; t < 1024; t += 256) {
            int n = t % 64, k = t / 64;
            int c = bn + n;
            float v = 0.f;
            if (c < 2 * HID) {
                int half = c / HID, h = c - half * HID;
                v = W1[(size_t)(half * DIM + k0 + k) * HID + h];
            }
            Bs[k][n] = v;
        }
        __syncthreads();
        #pragma unroll
        for (int k = 0; k < 16; ++k) {
            float a[4], bb[4];
            #pragma unroll
            for (int u = 0; u < 4; ++u) a[u] = As[k][ty * 4 + u];
            #pragma unroll
            for (int v = 0; v < 4; ++v) bb[v] = Bs[k][tx * 4 + v];
            #pragma unroll
            for (int u = 0; u < 4; ++u)
                #pragma unroll
                for (int v = 0; v < 4; ++v)
                    acc[u][v] = fmaf(a[u], bb[v], acc[u][v]);
        }
        __syncthreads();
    }
    #pragma unroll
    for (int u = 0; u < 4; ++u)
        #pragma unroll
        for (int v = 0; v < 4; ++v) {
            int c = bn + tx * 4 + v;
            if (c < 2 * HID)
                g_AB[(size_t)(bm + ty * 4 + u) * (2 * HID) + c] = acc[u][v];
        }
}

// ================= fused MLP (X fully smem-resident, FP8 MMA) =================
__global__ __launch_bounds__(256, 2)
void k_fused(const float* __restrict__ b1, const float* __restrict__ b2,
             const float* __restrict__ W3, const float* __restrict__ b3) {
    extern __shared__ __align__(16) char dynsm[];
    uint32_t dynbase = (uint32_t)__cvta_generic_to_shared(dynsm);
    uint32_t x_base = dynbase + X_OFF;
    uint32_t ws_base[2] = { dynbase + WS0_OFF, dynbase + WS1_OFF };
    uint32_t es_base = dynbase + ES_OFF;
    uint32_t hs_base = dynbase + HS_OFF;
    uint8_t* Xs = (uint8_t*)(dynsm + X_OFF);
    float*   Es = (float*)(dynsm + ES_OFF);              // [16][384] fp32 staging
    uint8_t* Hs = (uint8_t*)(dynsm + HS_OFF);

    __shared__ float b1s[HID], b2s[HID], W3s[HID];
    __shared__ float sred[MTILE][4];

    int tid = threadIdx.x;
    int b = blockIdx.y;

    // decode token block (bi, bj), bi >= bj
    int tb = blockIdx.x;
    int bi = (int)((sqrtf(8.0f * (float)tb + 1.0f) - 1.0f) * 0.5f);
    while (bi * (bi + 1) / 2 > tb) --bi;
    while ((bi + 1) * (bi + 2) / 2 <= tb) ++bi;
    int bj = tb - bi * (bi + 1) / 2;

    if (tid < HID) { b1s[tid] = b1[tid]; b2s[tid] = b2[tid]; W3s[tid] = W3[tid]; }

    const float* Eb = g_E + (size_t)b * NSEL * DIM;
    int wid = tid / 32, lane = tid % 32;
    int wm = wid & 1, wn = wid >> 1;
    int q = lane >> 2, l4 = lane & 3;

    // ldmatrix address components (bytes)
    int rowA  = wm * 32 + (lane & 15);         // + mt*16
    int colA  = (lane >> 4) * 16;
    int rowB8 = lane & 7;                      // + nt_g*8
    int colB4 = (lane >> 3) * 16;              // 0..48 (x4: both k32 halves)

    // ---------------- prologue A: build full X (two halves of 384 cols) ----------------
    #pragma unroll
    for (int h = 0; h < 2; ++h) {
        int hc = h * 384;
        // stage E fp32: 16 rows x 384 floats = 1536 segs of 16B
        #pragma unroll
        for (int u = 0; u < 6; ++u) {
            int seg = tid + u * 256;
            int row = seg / 96, sc = seg % 96;
            int tok = (row < 8) ? (bi * 8 + row) : (bj * 8 + row - 8);
            cpasync16(es_base + row * 1536 + sc * 16,
                      Eb + (size_t)tok * DIM + hc + sc * 4);
        }
        cpasync_commit();
        cpasync_wait0();
        __syncthreads();
        // build X cols [hc, hc+384): 6144 packs
        #pragma unroll
        for (int u = 0; u < 24; ++u) {
            int e = tid + u * 256;
            int row = e / 96, pc = e % 96;
            int ri = row >> 3, rj = row & 7;
            const float4 xi = *(const float4*)&Es[ri * 384 + pc * 4];
            const float4 xj = *(const float4*)&Es[(8 + rj) * 384 + pc * 4];
            *(uint32_t*)&Xs[row * XR + hc + pc * 4] =
                pack_e4m3_4(xi.x * xj.x, xi.y * xj.y, xi.z * xj.z, xi.w * xj.w);
        }
        __syncthreads();
    }

    float acc[2][7][4];
    #pragma unroll
    for (int mt = 0; mt < 2; ++mt)
        #pragma unroll
        for (int t = 0; t < 7; ++t)
            #pragma unroll
            for (int v = 0; v < 4; ++v) acc[mt][t][v] = 0.f;

    // ---------------- prologue B: W1 chunk 0 ----------------
    {
        #pragma unroll
        for (int u = 0; u < 4; ++u) {
            int e = tid + u * 256;
            if (e < HID * 4) {
                int n = e >> 2, seg = e & 3;
                cpasync16(ws_base[0] + n * WS_STRIDE + seg * 16,
                          g_W1q + (size_t)n * DIM + seg * 16);
            }
        }
        cpasync_commit();
        cpasync_wait0();
        __syncthreads();
    }

    // ---------------- layer-1 mainloop (12 chunks of 64 K; X resident) ----------------
    for (int c = 0; c < L1C; ++c) {
        uint32_t wsb = ws_base[c & 1];
        bool more = (c + 1 < L1C);
        if (more) {
            int c1 = (c + 1) * 64;
            #pragma unroll
            for (int u = 0; u < 4; ++u) {
                int e = tid + u * 256;
                if (e < HID * 4) {
                    int n = e >> 2, seg = e & 3;
                    cpasync16(ws_base[(c + 1) & 1] + n * WS_STRIDE + seg * 16,
                              g_W1q + (size_t)n * DIM + c1 + seg * 16);
                }
            }
            cpasync_commit();
        }
        // A fragments for both k32 steps
        uint32_t a[2][2][4];
        #pragma unroll
        for (int ks = 0; ks < 2; ++ks)
            #pragma unroll
            for (int mt = 0; mt < 2; ++mt)
                ldsm_x4(a[ks][mt],
                        x_base + (rowA + mt * 16) * XR + c * 64 + ks * 32 + colA);
        #pragma unroll
        for (int t = 0; t < 7; ++t) {
            int nt_g = wn + 4 * t;
            if (nt_g < NTILES) {
                uint32_t bb[4];
                ldsm_x4(bb, wsb + (nt_g * 8 + rowB8) * WS_STRIDE + colB4);
                #pragma unroll
                for (int ks = 0; ks < 2; ++ks)
                    #pragma unroll
                    for (int mt = 0; mt < 2; ++mt)
                        mma_fp8(acc[mt][t], a[ks][mt], bb + ks * 2);
            }
        }
        if (more) cpasync_wait0();
        __syncthreads();
    }

    // ---------------- layer-1 epilogue -> Hs (e4m3 x8); AB from global ----------------
    {
        const float* ABb = g_AB + (size_t)b * NSEL * (2 * HID);
        #pragma unroll
        for (int mt = 0; mt < 2; ++mt) {
            #pragma unroll
            for (int half = 0; half < 2; ++half) {
                int r = wm * 32 + mt * 16 + q + 8 * half;
                int ri = r >> 3, rj = r & 7;
                const float* Ai = ABb + (size_t)(bi * 8 + ri) * (2 * HID);
                const float* Bj = ABb + (size_t)(bj * 8 + rj) * (2 * HID) + HID;
                #pragma unroll
                for (int t = 0; t < 7; ++t) {
                    int nt_g = wn + 4 * t;
                    if (nt_g < NTILES) {
                        int col = nt_g * 8 + 2 * l4;
                        float2 ai = *(const float2*)(Ai + col);
                        float2 bj2 = *(const float2*)(Bj + col);
                        float v0 = acc[mt][t][half * 2 + 0] * INV_W + ai.x + bj2.x + b1s[col];
                        float v1 = acc[mt][t][half * 2 + 1] * INV_W + ai.y + bj2.y + b1s[col + 1];
                        uint16_t p = pack_e4m3_2(H_SCALE * fmaxf(v0, 0.f),
                                                 H_SCALE * fmaxf(v1, 0.f));
                        *(uint16_t*)(Hs + r * HS_STRIDE + col) = p;
                    }
                }
            }
        }
    }
    // zero pad cols [200,240)
    for (int e = tid; e < MTILE * 10; e += 256) {
        int r = e / 10, cc = HID + (e % 10) * 4;
        *(uint32_t*)(Hs + r * HS_STRIDE + cc) = 0u;
    }

    #pragma unroll
    for (int mt = 0; mt < 2; ++mt)
        #pragma unroll
        for (int t = 0; t < 7; ++t)
            #pragma unroll
            for (int v = 0; v < 4; ++v) acc[mt][t][v] = 0.f;

    // ---------------- layer-2 prologue ----------------
    {
        #pragma unroll
        for (int u = 0; u < 4; ++u) {
            int e = tid + u * 256;
            if (e < HID * 4) {
                int n = e >> 2, seg = e & 3;
                cpasync16(ws_base[0] + n * WS_STRIDE + seg * 16,
                          g_W2q + (size_t)n * K2PAD + seg * 16);
            }
        }
        cpasync_commit();
        cpasync_wait0();
        __syncthreads();            // covers Hs writes + W2(0)
    }
    // ---------------- layer-2 mainloop (A from Hs fp8) ----------------
    for (int c = 0; c < L2C; ++c) {
        uint32_t wsb = ws_base[c & 1];
        bool more = (c + 1 < L2C);
        if (more) {
            int c1 = (c + 1) * 64;
            #pragma unroll
            for (int u = 0; u < 4; ++u) {
                int e = tid + u * 256;
                if (e < HID * 4) {
                    int n = e >> 2, seg = e & 3;
                    cpasync16(ws_base[(c + 1) & 1] + n * WS_STRIDE + seg * 16,
                              g_W2q + (size_t)n * K2PAD + c1 + seg * 16);
                }
            }
            cpasync_commit();
        }
        uint32_t a[2][2][4];
        #pragma unroll
        for (int ks = 0; ks < 2; ++ks)
            #pragma unroll
            for (int mt = 0; mt < 2; ++mt)
                ldsm_x4(a[ks][mt],
                        hs_base + (rowA + mt * 16) * HS_STRIDE + c * 64 + ks * 32 + colA);
        #pragma unroll
        for (int t = 0; t < 7; ++t) {
            int nt_g = wn + 4 * t;
            if (nt_g < NTILES) {
                uint32_t bb[4];
                ldsm_x4(bb, wsb + (nt_g * 8 + rowB8) * WS_STRIDE + colB4);
                #pragma unroll
                for (int ks = 0; ks < 2; ++ks)
                    #pragma unroll
                    for (int mt = 0; mt < 2; ++mt)
                        mma_fp8(acc[mt][t], a[ks][mt], bb + ks * 2);
            }
        }
        if (more) cpasync_wait0();
        __syncthreads();
    }

    // ---------------- scoring epilogue ----------------
    #pragma unroll
    for (int mt = 0; mt < 2; ++mt) {
        #pragma unroll
        for (int half = 0; half < 2; ++half) {
            float sp = 0.f;
            #pragma unroll
            for (int t = 0; t < 7; ++t) {
                int nt_g = wn + 4 * t;
                if (nt_g < NTILES) {
                    int col = nt_g * 8 + 2 * l4;
                    float h0 = fmaxf(acc[mt][t][half * 2 + 0] * INV_HW + b2s[col], 0.f);
                    float h1 = fmaxf(acc[mt][t][half * 2 + 1] * INV_HW + b2s[col + 1], 0.f);
                    sp = fmaf(h0, W3s[col], sp);
                    sp = fmaf(h1, W3s[col + 1], sp);
                }
            }
            sp += __shfl_xor_sync(0xFFFFFFFFu, sp, 1);
            sp += __shfl_xor_sync(0xFFFFFFFFu, sp, 2);
            if (l4 == 0) {
                int r = wm * 32 + mt * 16 + q + 8 * half;
                sred[r][wn] = sp;
            }
        }
    }
    __syncthreads();
    if (tid < MTILE) {
        float s = sred[tid][0] + sred[tid][1] + sred[tid][2] + sred[tid][3] + b3[0];
        int i = bi * 8 + (tid >> 3), j = bj * 8 + (tid & 7);
        if (i > j)
            g_S[((size_t)b * NSEL + i) * NSEL + j] = s;
    }
}

// ---------------- row softmax + fill (warp per row) ----------------
__global__ void k_soft(float* __restrict__ out) {
    int wid = threadIdx.x / 32, lane = threadIdx.x % 32;
    int bn = blockIdx.x * 8 + wid;              // 128 blocks x 8 warps = 1024 rows
    int i = bn % NSEL;
    const float* Srow = g_S + (size_t)bn * NSEL;
    float* orow = out + (size_t)bn * NSEL;

    float l[8];
    float mx = -1e30f;
    #pragma unroll
    for (int u = 0; u < 8; ++u) {
        int j = lane + u * 32;
        if (j <= i) {
            l[u] = (j == i) ? 0.f : Srow[j];
            mx = fmaxf(mx, l[u]);
        } else {
            l[u] = -1e30f;
        }
    }
    #pragma unroll
    for (int s = 16; s > 0; s >>= 1)
        mx = fmaxf(mx, __shfl_xor_sync(0xFFFFFFFFu, mx, s));

    float e[8];
    float sum = 0.f;
    #pragma unroll
    for (int u = 0; u < 8; ++u) {
        int j = lane + u * 32;
        if (j <= i) {
            e[u] = __expf(l[u] - mx);
            sum += e[u];
        }
    }
    #pragma unroll
    for (int s = 16; s > 0; s >>= 1)
        sum += __shfl_xor_sync(0xFFFFFFFFu, sum, s);
    float inv = 1.0f / sum;

    #pragma unroll
    for (int u = 0; u < 8; ++u) {
        int j = lane + u * 32;
        orow[j] = (j <= i) ? e[u] * inv : -1000.0f;
    }
}

// ---------------- launch ----------------
extern "C" void kernel_launch(void* const* d_in, const int* in_sizes, int n_in,
                              void* d_out, int out_size) {
    const float* emb = (const float*)d_in[0];
    const int*   idx = (const int*)  d_in[1];
    const float* W1  = (const float*)d_in[2];
    const float* b1  = (const float*)d_in[3];
    const float* W2  = (const float*)d_in[4];
    const float* b2  = (const float*)d_in[5];
    const float* W3  = (const float*)d_in[6];
    const float* b3  = (const float*)d_in[7];
    float* out = (float*)d_out;

    static int configured = 0;
    if (!configured) {
        cudaFuncSetAttribute(k_fused, cudaFuncAttributeMaxDynamicSharedMemorySize,
                             DYN_BYTES);
        configured = 1;
    }

    k_prep<<<PREP_BLKS, 256>>>(emb, idx, W1, W2);
    k_ab<<<dim3(16, 7), 256>>>(W1);
    k_fused<<<dim3(NBLK, BATCH), 256, DYN_BYTES>>>(b1, b2, W3, b3);
    k_soft<<<BATCH * NSEL / 8, 256>>>(out);
}

// round 16
// speedup vs baseline: 1.4364x; 1.0857x over previous
#include <cuda_runtime.h>
#include <cuda_bf16.h>
#include <cuda_fp8.h>
#include <math.h>
#include <stdint.h>

#define BATCH 4
#define TLEN  4096
#define DIM   768
#define NSEL  256
#define HID   200
#define MTILE 64             // pairs per CTA (8x8 token block)
#define NB8   32
#define NBLK  528            // NB8*(NB8+1)/2
#define K2PAD 256
#define L1C   (DIM / 64)     // 12 chunks of 64 fp8
#define NTILES 25
#define XR    784            // X row stride bytes (768 + 16 pad), conflict-free
#define WS_STRIDE 80         // W chunk row stride bytes
#define HS_STRIDE 240        // Hs row stride bytes
#define W2S_STRIDE 240       // resident W2 row stride bytes (15x16B: conflict-free)

// dynamic smem layout (bytes)
#define X_OFF   0                      // 64*784 = 50176 (reused for whole W2 in layer 2)
#define WS0_OFF 50176                  // 200*80 = 16000
#define WS1_OFF 66176                  // 16000
#define HS_OFF  82176                  // 64*240 = 15360
#define DYN_BYTES 97536
#define ES_OFF  WS0_OFF                // E fp32 half staging overlays W ring (24576 <= 32000)

#define W_SCALE   32.0f
#define H_SCALE   8.0f
#define INV_W     (1.0f / 32.0f)
#define INV_HW    (1.0f / 256.0f)

// ---------------- device scratch ----------------
__device__ float    g_E  [BATCH * NSEL * DIM];
__device__ float    g_AB [BATCH * NSEL * 2 * HID];
__device__ uint8_t  g_W1q[HID * DIM];               // e4m3 of 32*W1c^T [h][d]
__device__ uint8_t  g_W2q[HID * K2PAD];             // e4m3 of 32*W2^T  [h][k]
__device__ float    g_S  [BATCH * NSEL * NSEL];

// ---------------- helpers ----------------
__device__ __forceinline__ void mma_fp8(float* c, const uint32_t* a, const uint32_t* b) {
    asm volatile(
        "mma.sync.aligned.m16n8k32.row.col.f32.e4m3.e4m3.f32 "
        "{%0,%1,%2,%3}, {%4,%5,%6,%7}, {%8,%9}, {%0,%1,%2,%3};"
        : "+f"(c[0]), "+f"(c[1]), "+f"(c[2]), "+f"(c[3])
        : "r"(a[0]), "r"(a[1]), "r"(a[2]), "r"(a[3]), "r"(b[0]), "r"(b[1]));
}
__device__ __forceinline__ void ldsm_x4(uint32_t* r, uint32_t addr) {
    asm volatile("ldmatrix.sync.aligned.m8n8.x4.shared.b16 {%0,%1,%2,%3}, [%4];"
                 : "=r"(r[0]), "=r"(r[1]), "=r"(r[2]), "=r"(r[3]) : "r"(addr));
}
__device__ __forceinline__ void cpasync16(uint32_t smem_addr, const void* gsrc) {
    asm volatile("cp.async.cg.shared.global [%0], [%1], 16;"
                 :: "r"(smem_addr), "l"(gsrc) : "memory");
}
__device__ __forceinline__ void cpasync_commit() {
    asm volatile("cp.async.commit_group;" ::: "memory");
}
__device__ __forceinline__ void cpasync_wait0() {
    asm volatile("cp.async.wait_group 0;" ::: "memory");
}
__device__ __forceinline__ uint32_t pack_e4m3_4(float a0, float a1, float a2, float a3) {
    uint16_t lo, hi;
    asm("cvt.rn.satfinite.e4m3x2.f32 %0, %1, %2;" : "=h"(lo) : "f"(a1), "f"(a0));
    asm("cvt.rn.satfinite.e4m3x2.f32 %0, %1, %2;" : "=h"(hi) : "f"(a3), "f"(a2));
    return (uint32_t)lo | ((uint32_t)hi << 16);
}
__device__ __forceinline__ uint16_t pack_e4m3_2(float a0, float a1) {
    uint16_t v;
    asm("cvt.rn.satfinite.e4m3x2.f32 %0, %1, %2;" : "=h"(v) : "f"(a1), "f"(a0));
    return v;
}
__device__ __forceinline__ uint8_t cvt_e4m3(float v) {
    return (uint8_t)__nv_cvt_float_to_fp8(v, __NV_SATFINITE, __NV_E4M3);
}

// ---------------- fused prep: gather + coalesced W transposes ----------------
#define PREP_GATH  (BATCH * NSEL)                       // 1024
#define PREP_W1T   (24 * 7)                             // (768/32) x ceil(200/32)
#define PREP_W2T   (8 * 7)                              // (256/32) x ceil(200/32)
#define PREP_BLKS  (PREP_GATH + PREP_W1T + PREP_W2T)

__global__ void k_prep(const float* __restrict__ emb, const int* __restrict__ idx,
                       const float* __restrict__ W1, const float* __restrict__ W2) {
    __shared__ float ts[32][33];
    int blk = blockIdx.x;
    int tid = threadIdx.x;
    if (blk < PREP_GATH) {
        int b = blk / NSEL, n = blk % NSEL;
        int t = idx[b * NSEL + n];
        const float4* src = (const float4*)(emb + ((size_t)b * TLEN + t) * DIM);
        float4* dst = (float4*)(g_E + (size_t)blk * DIM);
        if (tid < DIM / 4) dst[tid] = src[tid];
        return;
    }
    blk -= PREP_GATH;
    if (blk < PREP_W1T) {
        int dt = blk % 24, ht = blk / 24;
        int d0 = dt * 32, h0 = ht * 32;
        #pragma unroll
        for (int u = 0; u < 4; ++u) {
            int e = tid + u * 256;
            int dd = e >> 5, hh = e & 31;
            int h = h0 + hh;
            ts[dd][hh] = (h < HID)
                ? W_SCALE * W1[(size_t)(2 * DIM + d0 + dd) * HID + h] : 0.f;
        }
        __syncthreads();
        #pragma unroll
        for (int u = 0; u < 4; ++u) {
            int e = tid + u * 256;
            int hh = e >> 5, dd = e & 31;
            int h = h0 + hh;
            if (h < HID)
                g_W1q[(size_t)h * DIM + d0 + dd] = cvt_e4m3(ts[dd][hh]);
        }
        return;
    }
    blk -= PREP_W1T;
    {
        int kt = blk % 8, ht = blk / 8;
        int k0 = kt * 32, h0 = ht * 32;
        #pragma unroll
        for (int u = 0; u < 4; ++u) {
            int e = tid + u * 256;
            int kk = e >> 5, hh = e & 31;
            int h = h0 + hh, k = k0 + kk;
            ts[kk][hh] = (h < HID && k < HID)
                ? W_SCALE * W2[(size_t)k * HID + h] : 0.f;
        }
        __syncthreads();
        #pragma unroll
        for (int u = 0; u < 4; ++u) {
            int e = tid + u * 256;
            int hh = e >> 5, kk = e & 31;
            int h = h0 + hh;
            if (h < HID)
                g_W2q[(size_t)h * K2PAD + k0 + kk] = cvt_e4m3(ts[kk][hh]);
        }
    }
}

// ---------------- exact A/B partials (fp32 SIMT), BM=32 for full-chip spread ----------------
__global__ void k_ab(const float* __restrict__ W1) {
    __shared__ __align__(16) float As[16][32 + 4];
    __shared__ __align__(16) float Bs[16][64 + 4];
    int bm = blockIdx.x * 32, bn = blockIdx.y * 64;
    int tx = threadIdx.x % 16, ty = threadIdx.x / 16;   // ty 0..15
    float acc[2][4] = {};
    for (int k0 = 0; k0 < DIM; k0 += 16) {
        for (int t = threadIdx.x; t < 512; t += 256) {
            int k = t % 16, m = t / 16;
            As[k][m] = g_E[(size_t)(bm + m) * DIM + k0 + k];
        }
        for (int t = threadIdx.x; t < 1024; t += 256) {
            int n = t % 64, k = t / 64;
            int c = bn + n;
            float v = 0.f;
            if (c < 2 * HID) {
                int half = c / HID, h = c - half * HID;
                v = W1[(size_t)(half * DIM + k0 + k) * HID + h];
            }
            Bs[k][n] = v;
        }
        __syncthreads();
        #pragma unroll
        for (int k = 0; k < 16; ++k) {
            float a[2], bb[4];
            #pragma unroll
            for (int u = 0; u < 2; ++u) a[u] = As[k][ty * 2 + u];
            #pragma unroll
            for (int v = 0; v < 4; ++v) bb[v] = Bs[k][tx * 4 + v];
            #pragma unroll
            for (int u = 0; u < 2; ++u)
                #pragma unroll
                for (int v = 0; v < 4; ++v)
                    acc[u][v] = fmaf(a[u], bb[v], acc[u][v]);
        }
        __syncthreads();
    }
    #pragma unroll
    for (int u = 0; u < 2; ++u)
        #pragma unroll
        for (int v = 0; v < 4; ++v) {
            int c = bn + tx * 4 + v;
            if (c < 2 * HID)
                g_AB[(size_t)(bm + ty * 2 + u) * (2 * HID) + c] = acc[u][v];
        }
}

// ================= fused MLP (X resident L1; whole-W2 resident, barrier-free L2) =================
__global__ __launch_bounds__(256, 2)
void k_fused(const float* __restrict__ b1, const float* __restrict__ b2,
             const float* __restrict__ W3, const float* __restrict__ b3) {
    extern __shared__ __align__(16) char dynsm[];
    uint32_t dynbase = (uint32_t)__cvta_generic_to_shared(dynsm);
    uint32_t x_base = dynbase + X_OFF;
    uint32_t ws_base[2] = { dynbase + WS0_OFF, dynbase + WS1_OFF };
    uint32_t es_base = dynbase + ES_OFF;
    uint32_t hs_base = dynbase + HS_OFF;
    uint8_t* Xs = (uint8_t*)(dynsm + X_OFF);
    float*   Es = (float*)(dynsm + ES_OFF);              // [16][384] fp32 staging
    uint8_t* Hs = (uint8_t*)(dynsm + HS_OFF);

    __shared__ float b1s[HID], b2s[HID], W3s[HID];
    __shared__ float sred[MTILE][4];

    int tid = threadIdx.x;
    int b = blockIdx.y;

    // decode token block (bi, bj), bi >= bj
    int tb = blockIdx.x;
    int bi = (int)((sqrtf(8.0f * (float)tb + 1.0f) - 1.0f) * 0.5f);
    while (bi * (bi + 1) / 2 > tb) --bi;
    while ((bi + 1) * (bi + 2) / 2 <= tb) ++bi;
    int bj = tb - bi * (bi + 1) / 2;

    if (tid < HID) { b1s[tid] = b1[tid]; b2s[tid] = b2[tid]; W3s[tid] = W3[tid]; }

    const float* Eb = g_E + (size_t)b * NSEL * DIM;
    int wid = tid / 32, lane = tid % 32;
    int wm = wid & 1, wn = wid >> 1;
    int q = lane >> 2, l4 = lane & 3;

    // ldmatrix address components (bytes)
    int rowA  = wm * 32 + (lane & 15);         // + mt*16
    int colA  = (lane >> 4) * 16;
    int rowB8 = lane & 7;                      // + nt_g*8
    int colB4 = (lane >> 3) * 16;              // 0..48 (x4: both k32 halves)

    // ---------------- prologue A: build full X (two halves of 384 cols) ----------------
    #pragma unroll
    for (int h = 0; h < 2; ++h) {
        int hc = h * 384;
        #pragma unroll
        for (int u = 0; u < 6; ++u) {
            int seg = tid + u * 256;
            int row = seg / 96, sc = seg % 96;
            int tok = (row < 8) ? (bi * 8 + row) : (bj * 8 + row - 8);
            cpasync16(es_base + row * 1536 + sc * 16,
                      Eb + (size_t)tok * DIM + hc + sc * 4);
        }
        cpasync_commit();
        cpasync_wait0();
        __syncthreads();
        #pragma unroll
        for (int u = 0; u < 24; ++u) {
            int e = tid + u * 256;
            int row = e / 96, pc = e % 96;
            int ri = row >> 3, rj = row & 7;
            const float4 xi = *(const float4*)&Es[ri * 384 + pc * 4];
            const float4 xj = *(const float4*)&Es[(8 + rj) * 384 + pc * 4];
            *(uint32_t*)&Xs[row * XR + hc + pc * 4] =
                pack_e4m3_4(xi.x * xj.x, xi.y * xj.y, xi.z * xj.z, xi.w * xj.w);
        }
        __syncthreads();
    }

    float acc[2][7][4];
    #pragma unroll
    for (int mt = 0; mt < 2; ++mt)
        #pragma unroll
        for (int t = 0; t < 7; ++t)
            #pragma unroll
            for (int v = 0; v < 4; ++v) acc[mt][t][v] = 0.f;

    // ---------------- prologue B: W1 chunk 0 ----------------
    {
        #pragma unroll
        for (int u = 0; u < 4; ++u) {
            int e = tid + u * 256;
            if (e < HID * 4) {
                int n = e >> 2, seg = e & 3;
                cpasync16(ws_base[0] + n * WS_STRIDE + seg * 16,
                          g_W1q + (size_t)n * DIM + seg * 16);
            }
        }
        cpasync_commit();
        cpasync_wait0();
        __syncthreads();
    }

    // ---------------- layer-1 mainloop (12 chunks of 64 K; X resident) ----------------
    for (int c = 0; c < L1C; ++c) {
        uint32_t wsb = ws_base[c & 1];
        bool more = (c + 1 < L1C);
        if (more) {
            int c1 = (c + 1) * 64;
            #pragma unroll
            for (int u = 0; u < 4; ++u) {
                int e = tid + u * 256;
                if (e < HID * 4) {
                    int n = e >> 2, seg = e & 3;
                    cpasync16(ws_base[(c + 1) & 1] + n * WS_STRIDE + seg * 16,
                              g_W1q + (size_t)n * DIM + c1 + seg * 16);
                }
            }
            cpasync_commit();
        }
        uint32_t a[2][2][4];
        #pragma unroll
        for (int ks = 0; ks < 2; ++ks)
            #pragma unroll
            for (int mt = 0; mt < 2; ++mt)
                ldsm_x4(a[ks][mt],
                        x_base + (rowA + mt * 16) * XR + c * 64 + ks * 32 + colA);
        #pragma unroll
        for (int t = 0; t < 7; ++t) {
            int nt_g = wn + 4 * t;
            if (nt_g < NTILES) {
                uint32_t bb[4];
                ldsm_x4(bb, wsb + (nt_g * 8 + rowB8) * WS_STRIDE + colB4);
                #pragma unroll
                for (int ks = 0; ks < 2; ++ks)
                    #pragma unroll
                    for (int mt = 0; mt < 2; ++mt)
                        mma_fp8(acc[mt][t], a[ks][mt], bb + ks * 2);
            }
        }
        if (more) cpasync_wait0();
        __syncthreads();
    }

    // X region now dead: start whole-W2 load (overlaps the epilogue below).
    // 200 rows x 224 bytes -> stride 240 (conflict-free). 2800 16B segments.
    #pragma unroll
    for (int u = 0; u < 11; ++u) {
        int seg = tid + u * 256;
        if (seg < 2800) {
            int row = seg / 14, sc = seg % 14;
            cpasync16(x_base + row * W2S_STRIDE + sc * 16,
                      g_W2q + (size_t)row * K2PAD + sc * 16);
        }
    }
    cpasync_commit();

    // ---------------- layer-1 epilogue -> Hs (e4m3 x8); AB from global ----------------
    {
        const float* ABb = g_AB + (size_t)b * NSEL * (2 * HID);
        #pragma unroll
        for (int mt = 0; mt < 2; ++mt) {
            #pragma unroll
            for (int half = 0; half < 2; ++half) {
                int r = wm * 32 + mt * 16 + q + 8 * half;
                int ri = r >> 3, rj = r & 7;
                const float* Ai = ABb + (size_t)(bi * 8 + ri) * (2 * HID);
                const float* Bj = ABb + (size_t)(bj * 8 + rj) * (2 * HID) + HID;
                #pragma unroll
                for (int t = 0; t < 7; ++t) {
                    int nt_g = wn + 4 * t;
                    if (nt_g < NTILES) {
                        int col = nt_g * 8 + 2 * l4;
                        float2 ai = *(const float2*)(Ai + col);
                        float2 bj2 = *(const float2*)(Bj + col);
                        float v0 = acc[mt][t][half * 2 + 0] * INV_W + ai.x + bj2.x + b1s[col];
                        float v1 = acc[mt][t][half * 2 + 1] * INV_W + ai.y + bj2.y + b1s[col + 1];
                        uint16_t p = pack_e4m3_2(H_SCALE * fmaxf(v0, 0.f),
                                                 H_SCALE * fmaxf(v1, 0.f));
                        *(uint16_t*)(Hs + r * HS_STRIDE + col) = p;
                    }
                }
            }
        }
    }
    // zero pad cols [200,240)
    for (int e = tid; e < MTILE * 10; e += 256) {
        int r = e / 10, cc = HID + (e % 10) * 4;
        *(uint32_t*)(Hs + r * HS_STRIDE + cc) = 0u;
    }

    #pragma unroll
    for (int mt = 0; mt < 2; ++mt)
        #pragma unroll
        for (int t = 0; t < 7; ++t)
            #pragma unroll
            for (int v = 0; v < 4; ++v) acc[mt][t][v] = 0.f;

    cpasync_wait0();
    __syncthreads();    // Hs + resident W2 both ready

    // ---------------- layer-2 mainloop: BARRIER-FREE (Hs & W2s read-only) ----------------
    // K2 = 224: chunks 0..2 full (2 k32 steps), chunk 3 half (1 step).
    #pragma unroll
    for (int c = 0; c < 4; ++c) {
        int nks = (c == 3) ? 1 : 2;
        uint32_t a[2][2][4];
        #pragma unroll
        for (int ks = 0; ks < 2; ++ks)
            if (ks < nks)
                #pragma unroll
                for (int mt = 0; mt < 2; ++mt)
                    ldsm_x4(a[ks][mt],
                            hs_base + (rowA + mt * 16) * HS_STRIDE + c * 64 + ks * 32 + colA);
        #pragma unroll
        for (int t = 0; t < 7; ++t) {
            int nt_g = wn + 4 * t;
            if (nt_g < NTILES) {
                uint32_t bb[4];
                ldsm_x4(bb, x_base + (nt_g * 8 + rowB8) * W2S_STRIDE + c * 64 + colB4);
                #pragma unroll
                for (int ks = 0; ks < 2; ++ks)
                    if (ks < nks)
                        #pragma unroll
                        for (int mt = 0; mt < 2; ++mt)
                            mma_fp8(acc[mt][t], a[ks][mt], bb + ks * 2);
            }
        }
    }

    // ---------------- scoring epilogue ----------------
    #pragma unroll
    for (int mt = 0; mt < 2; ++mt) {
        #pragma unroll
        for (int half = 0; half < 2; ++half) {
            float sp = 0.f;
            #pragma unroll
            for (int t = 0; t < 7; ++t) {
                int nt_g = wn + 4 * t;
                if (nt_g < NTILES) {
                    int col = nt_g * 8 + 2 * l4;
                    float h0 = fmaxf(acc[mt][t][half * 2 + 0] * INV_HW + b2s[col], 0.f);
                    float h1 = fmaxf(acc[mt][t][half * 2 + 1] * INV_HW + b2s[col + 1], 0.f);
                    sp = fmaf(h0, W3s[col], sp);
                    sp = fmaf(h1, W3s[col + 1], sp);
                }
            }
            sp += __shfl_xor_sync(0xFFFFFFFFu, sp, 1);
            sp += __shfl_xor_sync(0xFFFFFFFFu, sp, 2);
            if (l4 == 0) {
                int r = wm * 32 + mt * 16 + q + 8 * half;
                sred[r][wn] = sp;
            }
        }
    }
    __syncthreads();
    if (tid < MTILE) {
        float s = sred[tid][0] + sred[tid][1] + sred[tid][2] + sred[tid][3] + b3[0];
        int i = bi * 8 + (tid >> 3), j = bj * 8 + (tid & 7);
        if (i > j)
            g_S[((size_t)b * NSEL + i) * NSEL + j] = s;
    }
}

// ---------------- row softmax + fill (block per row) ----------------
__global__ void k_soft(float* __restrict__ out) {
    int bn = blockIdx.x;
    int i = bn % NSEL;
    const float* Srow = g_S + (size_t)bn * NSEL;
    float* orow = out + (size_t)bn * NSEL;
    __shared__ float red[256];
    int tid = threadIdx.x;

    float mx = -1e30f;
    for (int j = tid; j <= i; j += 256) {
        float l = (j == i) ? 0.f : Srow[j];
        mx = fmaxf(mx, l);
    }
    red[tid] = mx; __syncthreads();
    for (int s = 128; s > 0; s >>= 1) {
        if (tid < s) red[tid] = fmaxf(red[tid], red[tid + s]);
        __syncthreads();
    }
    mx = red[0]; __syncthreads();

    float sum = 0.f;
    for (int j = tid; j <= i; j += 256) {
        float l = (j == i) ? 0.f : Srow[j];
        sum += __expf(l - mx);
    }
    red[tid] = sum; __syncthreads();
    for (int s = 128; s > 0; s >>= 1) {
        if (tid < s) red[tid] += red[tid + s];
        __syncthreads();
    }
    sum = red[0];
    float inv = 1.0f / sum;

    for (int j = tid; j < NSEL; j += 256) {
        if (j <= i) {
            float l = (j == i) ? 0.f : Srow[j];
            orow[j] = __expf(l - mx) * inv;
        } else {
            orow[j] = -1000.0f;
        }
    }
}

// ---------------- launch ----------------
extern "C" void kernel_launch(void* const* d_in, const int* in_sizes, int n_in,
                              void* d_out, int out_size) {
    const float* emb = (const float*)d_in[0];
    const int*   idx = (const int*)  d_in[1];
    const float* W1  = (const float*)d_in[2];
    const float* b1  = (const float*)d_in[3];
    const float* W2  = (const float*)d_in[4];
    const float* b2  = (const float*)d_in[5];
    const float* W3  = (const float*)d_in[6];
    const float* b3  = (const float*)d_in[7];
    float* out = (float*)d_out;

    static int configured = 0;
    if (!configured) {
        cudaFuncSetAttribute(k_fused, cudaFuncAttributeMaxDynamicSharedMemorySize,
                             DYN_BYTES);
        configured = 1;
    }

    k_prep<<<PREP_BLKS, 256>>>(emb, idx, W1, W2);
    k_ab<<<dim3(32, 7), 256>>>(W1);
    k_fused<<<dim3(NBLK, BATCH), 256, DYN_BYTES>>>(b1, b2, W3, b3);
    k_soft<<<BATCH * NSEL, 256>>>(out);
}

// round 17
// speedup vs baseline: 1.8307x; 1.2745x over previous
#include <cuda_runtime.h>
#include <cuda_bf16.h>
#include <cuda_fp8.h>
#include <math.h>
#include <stdint.h>

#define BATCH 4
#define TLEN  4096
#define DIM   768
#define NSEL  256
#define HID   200
#define MTILE 64             // pairs per CTA (8x8 token block)
#define NB8   32
#define NBLK  528            // NB8*(NB8+1)/2
#define K2PAD 256
#define L1C   (DIM / 64)     // 12 chunks of 64 fp8
#define NTILES 25
#define XR    784            // X row stride bytes (768 + 16 pad), conflict-free
#define WS_STRIDE 80         // W chunk row stride bytes
#define HS_STRIDE 240        // Hs row stride bytes
#define W2S_STRIDE 240       // resident W2 row stride bytes

// k_fused dynamic smem layout (bytes)
#define X_OFF   0                      // 64*784 = 50176 (reused for whole W2 in layer 2)
#define WS0_OFF 50176                  // 200*80 = 16000
#define WS1_OFF 66176                  // 16000
#define HS_OFF  82176                  // 64*240 = 15360
#define DYN_BYTES 97536
#define ES_OFF  WS0_OFF                // E fp32 half staging overlays W ring

// k_abm dynamic smem layout (bytes)
#define AB_NT   50                     // 400/8 n-tiles
#define EB_STRIDE 1552                 // 768 bf16 = 1536 B + 16 pad (conflict-free)
#define EB_OFF  0                      // 32*1552 = 49664
#define AW0_OFF 49664                  // 400*80 = 32000
#define AW1_OFF 81664                  // 32000
#define DYN2_BYTES 113664

#define W_SCALE   32.0f
#define H_SCALE   8.0f
#define INV_W     (1.0f / 32.0f)
#define INV_HW    (1.0f / 256.0f)

// ---------------- device scratch ----------------
__device__ float          g_E  [BATCH * NSEL * DIM];
__device__ __nv_bfloat16  g_Ebf[BATCH * NSEL * DIM];   // gathered E, bf16
__device__ __nv_bfloat16  g_Wab[2 * HID * DIM];        // [c][d] K-major bf16 (c<400)
__device__ float          g_AB [BATCH * NSEL * 2 * HID];
__device__ uint8_t        g_W1q[HID * DIM];            // e4m3 of 32*W1c^T [h][d]
__device__ uint8_t        g_W2q[HID * K2PAD];          // e4m3 of 32*W2^T  [h][k]
__device__ float          g_S  [BATCH * NSEL * NSEL];

// ---------------- helpers ----------------
__device__ __forceinline__ void mma_fp8(float* c, const uint32_t* a, const uint32_t* b) {
    asm volatile(
        "mma.sync.aligned.m16n8k32.row.col.f32.e4m3.e4m3.f32 "
        "{%0,%1,%2,%3}, {%4,%5,%6,%7}, {%8,%9}, {%0,%1,%2,%3};"
        : "+f"(c[0]), "+f"(c[1]), "+f"(c[2]), "+f"(c[3])
        : "r"(a[0]), "r"(a[1]), "r"(a[2]), "r"(a[3]), "r"(b[0]), "r"(b[1]));
}
__device__ __forceinline__ void mma_bf16(float* c, const uint32_t* a, const uint32_t* b) {
    asm volatile(
        "mma.sync.aligned.m16n8k16.row.col.f32.bf16.bf16.f32 "
        "{%0,%1,%2,%3}, {%4,%5,%6,%7}, {%8,%9}, {%0,%1,%2,%3};"
        : "+f"(c[0]), "+f"(c[1]), "+f"(c[2]), "+f"(c[3])
        : "r"(a[0]), "r"(a[1]), "r"(a[2]), "r"(a[3]), "r"(b[0]), "r"(b[1]));
}
__device__ __forceinline__ void ldsm_x4(uint32_t* r, uint32_t addr) {
    asm volatile("ldmatrix.sync.aligned.m8n8.x4.shared.b16 {%0,%1,%2,%3}, [%4];"
                 : "=r"(r[0]), "=r"(r[1]), "=r"(r[2]), "=r"(r[3]) : "r"(addr));
}
__device__ __forceinline__ void cpasync16(uint32_t smem_addr, const void* gsrc) {
    asm volatile("cp.async.cg.shared.global [%0], [%1], 16;"
                 :: "r"(smem_addr), "l"(gsrc) : "memory");
}
__device__ __forceinline__ void cpasync_commit() {
    asm volatile("cp.async.commit_group;" ::: "memory");
}
__device__ __forceinline__ void cpasync_wait0() {
    asm volatile("cp.async.wait_group 0;" ::: "memory");
}
__device__ __forceinline__ uint32_t pack_e4m3_4(float a0, float a1, float a2, float a3) {
    uint16_t lo, hi;
    asm("cvt.rn.satfinite.e4m3x2.f32 %0, %1, %2;" : "=h"(lo) : "f"(a1), "f"(a0));
    asm("cvt.rn.satfinite.e4m3x2.f32 %0, %1, %2;" : "=h"(hi) : "f"(a3), "f"(a2));
    return (uint32_t)lo | ((uint32_t)hi << 16);
}
__device__ __forceinline__ uint16_t pack_e4m3_2(float a0, float a1) {
    uint16_t v;
    asm("cvt.rn.satfinite.e4m3x2.f32 %0, %1, %2;" : "=h"(v) : "f"(a1), "f"(a0));
    return v;
}
__device__ __forceinline__ uint8_t cvt_e4m3(float v) {
    return (uint8_t)__nv_cvt_float_to_fp8(v, __NV_SATFINITE, __NV_E4M3);
}

// ---------------- fused prep ----------------
#define PREP_GATH  (BATCH * NSEL)                       // 1024
#define PREP_W1T   (24 * 7)                             // 168
#define PREP_W2T   (8 * 7)                              // 56
#define PREP_WABT  (24 * 13)                            // 312
#define PREP_BLKS  (PREP_GATH + PREP_W1T + PREP_W2T + PREP_WABT)

__global__ void k_prep(const float* __restrict__ emb, const int* __restrict__ idx,
                       const float* __restrict__ W1, const float* __restrict__ W2) {
    __shared__ float ts[32][33];
    int blk = blockIdx.x;
    int tid = threadIdx.x;
    if (blk < PREP_GATH) {
        int b = blk / NSEL, n = blk % NSEL;
        int t = idx[b * NSEL + n];
        const float4* src = (const float4*)(emb + ((size_t)b * TLEN + t) * DIM);
        float4* dst = (float4*)(g_E + (size_t)blk * DIM);
        if (tid < DIM / 4) {
            float4 v = src[tid];
            dst[tid] = v;
            __nv_bfloat162 p0 = __floats2bfloat162_rn(v.x, v.y);
            __nv_bfloat162 p1 = __floats2bfloat162_rn(v.z, v.w);
            uint32_t* db = (uint32_t*)(g_Ebf + (size_t)blk * DIM + tid * 4);
            db[0] = *(uint32_t*)&p0;
            db[1] = *(uint32_t*)&p1;
        }
        return;
    }
    blk -= PREP_GATH;
    if (blk < PREP_W1T) {
        int dt = blk % 24, ht = blk / 24;
        int d0 = dt * 32, h0 = ht * 32;
        #pragma unroll
        for (int u = 0; u < 4; ++u) {
            int e = tid + u * 256;
            int dd = e >> 5, hh = e & 31;
            int h = h0 + hh;
            ts[dd][hh] = (h < HID)
                ? W_SCALE * W1[(size_t)(2 * DIM + d0 + dd) * HID + h] : 0.f;
        }
        __syncthreads();
        #pragma unroll
        for (int u = 0; u < 4; ++u) {
            int e = tid + u * 256;
            int hh = e >> 5, dd = e & 31;
            int h = h0 + hh;
            if (h < HID)
                g_W1q[(size_t)h * DIM + d0 + dd] = cvt_e4m3(ts[dd][hh]);
        }
        return;
    }
    blk -= PREP_W1T;
    if (blk < PREP_W2T) {
        int kt = blk % 8, ht = blk / 8;
        int k0 = kt * 32, h0 = ht * 32;
        #pragma unroll
        for (int u = 0; u < 4; ++u) {
            int e = tid + u * 256;
            int kk = e >> 5, hh = e & 31;
            int h = h0 + hh, k = k0 + kk;
            ts[kk][hh] = (h < HID && k < HID)
                ? W_SCALE * W2[(size_t)k * HID + h] : 0.f;
        }
        __syncthreads();
        #pragma unroll
        for (int u = 0; u < 4; ++u) {
            int e = tid + u * 256;
            int hh = e >> 5, kk = e & 31;
            int h = h0 + hh;
            if (h < HID)
                g_W2q[(size_t)h * K2PAD + k0 + kk] = cvt_e4m3(ts[kk][hh]);
        }
        return;
    }
    blk -= PREP_W2T;
    {
        // Wab transpose: rows c in [0,400) = (half, h), K-major over d. bf16.
        int dt = blk % 24, ct = blk / 24;
        int d0 = dt * 32, c0 = ct * 32;
        #pragma unroll
        for (int u = 0; u < 4; ++u) {
            int e = tid + u * 256;
            int dd = e >> 5, hh = e & 31;
            int c = c0 + hh;
            float v = 0.f;
            if (c < 2 * HID) {
                int half = c / HID, h = c - half * HID;
                v = W1[(size_t)(half * DIM + d0 + dd) * HID + h];
            }
            ts[dd][hh] = v;
        }
        __syncthreads();
        #pragma unroll
        for (int u = 0; u < 4; ++u) {
            int e = tid + u * 256;
            int hh = e >> 5, dd = e & 31;
            int c = c0 + hh;
            if (c < 2 * HID)
                g_Wab[(size_t)c * DIM + d0 + dd] = __float2bfloat16(ts[dd][hh]);
        }
    }
}

// ---------------- A/B partials via bf16 tensor mma ----------------
// 32 CTAs x 32 rows; N=400 in 50 tiles of 8; 8 warps each own nt = wid + 8t.
__global__ __launch_bounds__(256)
void k_abm() {
    extern __shared__ __align__(16) char dynsm[];
    uint32_t dynbase = (uint32_t)__cvta_generic_to_shared(dynsm);
    uint32_t eb_base = dynbase + EB_OFF;
    uint32_t aw_base[2] = { dynbase + AW0_OFF, dynbase + AW1_OFF };

    int tid = threadIdx.x;
    int m0 = blockIdx.x * 32;
    int wid = tid / 32, lane = tid % 32;
    int q = lane >> 2, l4 = lane & 3;

    int rowA = lane & 15;                    // + mt*16
    int colA = (lane >> 4) * 16;             // bytes (k16 half select)
    int rowB8 = lane & 7;                    // + nt*8
    int colB4 = (lane >> 3) * 16;            // bytes: x4 covers k32 (2 k16 steps)

    // prologue: E tile (32 x 1536B) + W chunk 0
    #pragma unroll
    for (int u = 0; u < 12; ++u) {
        int seg = tid + u * 256;             // 3072 segs
        int row = seg / 96, sc = seg % 96;
        cpasync16(eb_base + row * EB_STRIDE + sc * 16,
                  g_Ebf + (size_t)(m0 + row) * DIM + sc * 8);
    }
    #pragma unroll
    for (int u = 0; u < 7; ++u) {
        int seg = tid + u * 256;             // 1600 segs
        if (seg < 1600) {
            int row = seg >> 2, sc = seg & 3;
            cpasync16(aw_base[0] + row * WS_STRIDE + sc * 16,
                      g_Wab + (size_t)row * DIM + sc * 8);
        }
    }
    cpasync_commit();
    cpasync_wait0();
    __syncthreads();

    float acc[2][7][4];
    #pragma unroll
    for (int mt = 0; mt < 2; ++mt)
        #pragma unroll
        for (int t = 0; t < 7; ++t)
            #pragma unroll
            for (int v = 0; v < 4; ++v) acc[mt][t][v] = 0.f;

    for (int c = 0; c < DIM / 32; ++c) {     // 24 chunks of 32 bf16
        uint32_t awb = aw_base[c & 1];
        bool more = (c + 1 < DIM / 32);
        if (more) {
            int c1 = (c + 1) * 32;
            #pragma unroll
            for (int u = 0; u < 7; ++u) {
                int seg = tid + u * 256;
                if (seg < 1600) {
                    int row = seg >> 2, sc = seg & 3;
                    cpasync16(aw_base[(c + 1) & 1] + row * WS_STRIDE + sc * 16,
                              g_Wab + (size_t)row * DIM + c1 + sc * 8);
                }
            }
            cpasync_commit();
        }
        uint32_t a[2][2][4];                 // [ks][mt]
        #pragma unroll
        for (int ks = 0; ks < 2; ++ks)
            #pragma unroll
            for (int mt = 0; mt < 2; ++mt)
                ldsm_x4(a[ks][mt],
                        eb_base + (rowA + mt * 16) * EB_STRIDE + c * 64 + ks * 32 + colA);
        #pragma unroll
        for (int t = 0; t < 7; ++t) {
            int nt = wid + 8 * t;
            if (nt < AB_NT) {
                uint32_t bb[4];
                ldsm_x4(bb, awb + (nt * 8 + rowB8) * WS_STRIDE + colB4);
                #pragma unroll
                for (int ks = 0; ks < 2; ++ks)
                    #pragma unroll
                    for (int mt = 0; mt < 2; ++mt)
                        mma_bf16(acc[mt][t], a[ks][mt], bb + ks * 2);
            }
        }
        if (more) cpasync_wait0();
        __syncthreads();
    }

    // epilogue: store fp32 partials
    #pragma unroll
    for (int mt = 0; mt < 2; ++mt) {
        #pragma unroll
        for (int half = 0; half < 2; ++half) {
            int r = mt * 16 + q + 8 * half;
            float* dst = g_AB + (size_t)(m0 + r) * (2 * HID);
            #pragma unroll
            for (int t = 0; t < 7; ++t) {
                int nt = wid + 8 * t;
                if (nt < AB_NT) {
                    int col = nt * 8 + 2 * l4;
                    float2 v = make_float2(acc[mt][t][half * 2 + 0],
                                           acc[mt][t][half * 2 + 1]);
                    *(float2*)(dst + col) = v;
                }
            }
        }
    }
}

// ================= fused MLP (unchanged from R16) =================
__global__ __launch_bounds__(256, 2)
void k_fused(const float* __restrict__ b1, const float* __restrict__ b2,
             const float* __restrict__ W3, const float* __restrict__ b3) {
    extern __shared__ __align__(16) char dynsm[];
    uint32_t dynbase = (uint32_t)__cvta_generic_to_shared(dynsm);
    uint32_t x_base = dynbase + X_OFF;
    uint32_t ws_base[2] = { dynbase + WS0_OFF, dynbase + WS1_OFF };
    uint32_t es_base = dynbase + ES_OFF;
    uint32_t hs_base = dynbase + HS_OFF;
    uint8_t* Xs = (uint8_t*)(dynsm + X_OFF);
    float*   Es = (float*)(dynsm + ES_OFF);
    uint8_t* Hs = (uint8_t*)(dynsm + HS_OFF);

    __shared__ float b1s[HID], b2s[HID], W3s[HID];
    __shared__ float sred[MTILE][4];

    int tid = threadIdx.x;
    int b = blockIdx.y;

    int tb = blockIdx.x;
    int bi = (int)((sqrtf(8.0f * (float)tb + 1.0f) - 1.0f) * 0.5f);
    while (bi * (bi + 1) / 2 > tb) --bi;
    while ((bi + 1) * (bi + 2) / 2 <= tb) ++bi;
    int bj = tb - bi * (bi + 1) / 2;

    if (tid < HID) { b1s[tid] = b1[tid]; b2s[tid] = b2[tid]; W3s[tid] = W3[tid]; }

    const float* Eb = g_E + (size_t)b * NSEL * DIM;
    int wid = tid / 32, lane = tid % 32;
    int wm = wid & 1, wn = wid >> 1;
    int q = lane >> 2, l4 = lane & 3;

    int rowA  = wm * 32 + (lane & 15);
    int colA  = (lane >> 4) * 16;
    int rowB8 = lane & 7;
    int colB4 = (lane >> 3) * 16;

    #pragma unroll
    for (int h = 0; h < 2; ++h) {
        int hc = h * 384;
        #pragma unroll
        for (int u = 0; u < 6; ++u) {
            int seg = tid + u * 256;
            int row = seg / 96, sc = seg % 96;
            int tok = (row < 8) ? (bi * 8 + row) : (bj * 8 + row - 8);
            cpasync16(es_base + row * 1536 + sc * 16,
                      Eb + (size_t)tok * DIM + hc + sc * 4);
        }
        cpasync_commit();
        cpasync_wait0();
        __syncthreads();
        #pragma unroll
        for (int u = 0; u < 24; ++u) {
            int e = tid + u * 256;
            int row = e / 96, pc = e % 96;
            int ri = row >> 3, rj = row & 7;
            const float4 xi = *(const float4*)&Es[ri * 384 + pc * 4];
            const float4 xj = *(const float4*)&Es[(8 + rj) * 384 + pc * 4];
            *(uint32_t*)&Xs[row * XR + hc + pc * 4] =
                pack_e4m3_4(xi.x * xj.x, xi.y * xj.y, xi.z * xj.z, xi.w * xj.w);
        }
        __syncthreads();
    }

    float acc[2][7][4];
    #pragma unroll
    for (int mt = 0; mt < 2; ++mt)
        #pragma unroll
        for (int t = 0; t < 7; ++t)
            #pragma unroll
            for (int v = 0; v < 4; ++v) acc[mt][t][v] = 0.f;

    {
        #pragma unroll
        for (int u = 0; u < 4; ++u) {
            int e = tid + u * 256;
            if (e < HID * 4) {
                int n = e >> 2, seg = e & 3;
                cpasync16(ws_base[0] + n * WS_STRIDE + seg * 16,
                          g_W1q + (size_t)n * DIM + seg * 16);
            }
        }
        cpasync_commit();
        cpasync_wait0();
        __syncthreads();
    }

    for (int c = 0; c < L1C; ++c) {
        uint32_t wsb = ws_base[c & 1];
        bool more = (c + 1 < L1C);
        if (more) {
            int c1 = (c + 1) * 64;
            #pragma unroll
            for (int u = 0; u < 4; ++u) {
                int e = tid + u * 256;
                if (e < HID * 4) {
                    int n = e >> 2, seg = e & 3;
                    cpasync16(ws_base[(c + 1) & 1] + n * WS_STRIDE + seg * 16,
                              g_W1q + (size_t)n * DIM + c1 + seg * 16);
                }
            }
            cpasync_commit();
        }
        uint32_t a[2][2][4];
        #pragma unroll
        for (int ks = 0; ks < 2; ++ks)
            #pragma unroll
            for (int mt = 0; mt < 2; ++mt)
                ldsm_x4(a[ks][mt],
                        x_base + (rowA + mt * 16) * XR + c * 64 + ks * 32 + colA);
        #pragma unroll
        for (int t = 0; t < 7; ++t) {
            int nt_g = wn + 4 * t;
            if (nt_g < NTILES) {
                uint32_t bb[4];
                ldsm_x4(bb, wsb + (nt_g * 8 + rowB8) * WS_STRIDE + colB4);
                #pragma unroll
                for (int ks = 0; ks < 2; ++ks)
                    #pragma unroll
                    for (int mt = 0; mt < 2; ++mt)
                        mma_fp8(acc[mt][t], a[ks][mt], bb + ks * 2);
            }
        }
        if (more) cpasync_wait0();
        __syncthreads();
    }

    #pragma unroll
    for (int u = 0; u < 11; ++u) {
        int seg = tid + u * 256;
        if (seg < 2800) {
            int row = seg / 14, sc = seg % 14;
            cpasync16(x_base + row * W2S_STRIDE + sc * 16,
                      g_W2q + (size_t)row * K2PAD + sc * 16);
        }
    }
    cpasync_commit();

    {
        const float* ABb = g_AB + (size_t)b * NSEL * (2 * HID);
        #pragma unroll
        for (int mt = 0; mt < 2; ++mt) {
            #pragma unroll
            for (int half = 0; half < 2; ++half) {
                int r = wm * 32 + mt * 16 + q + 8 * half;
                int ri = r >> 3, rj = r & 7;
                const float* Ai = ABb + (size_t)(bi * 8 + ri) * (2 * HID);
                const float* Bj = ABb + (size_t)(bj * 8 + rj) * (2 * HID) + HID;
                #pragma unroll
                for (int t = 0; t < 7; ++t) {
                    int nt_g = wn + 4 * t;
                    if (nt_g < NTILES) {
                        int col = nt_g * 8 + 2 * l4;
                        float2 ai = *(const float2*)(Ai + col);
                        float2 bj2 = *(const float2*)(Bj + col);
                        float v0 = acc[mt][t][half * 2 + 0] * INV_W + ai.x + bj2.x + b1s[col];
                        float v1 = acc[mt][t][half * 2 + 1] * INV_W + ai.y + bj2.y + b1s[col + 1];
                        uint16_t p = pack_e4m3_2(H_SCALE * fmaxf(v0, 0.f),
                                                 H_SCALE * fmaxf(v1, 0.f));
                        *(uint16_t*)(Hs + r * HS_STRIDE + col) = p;
                    }
                }
            }
        }
    }
    for (int e = tid; e < MTILE * 10; e += 256) {
        int r = e / 10, cc = HID + (e % 10) * 4;
        *(uint32_t*)(Hs + r * HS_STRIDE + cc) = 0u;
    }

    #pragma unroll
    for (int mt = 0; mt < 2; ++mt)
        #pragma unroll
        for (int t = 0; t < 7; ++t)
            #pragma unroll
            for (int v = 0; v < 4; ++v) acc[mt][t][v] = 0.f;

    cpasync_wait0();
    __syncthreads();

    #pragma unroll
    for (int c = 0; c < 4; ++c) {
        int nks = (c == 3) ? 1 : 2;
        uint32_t a[2][2][4];
        #pragma unroll
        for (int ks = 0; ks < 2; ++ks)
            if (ks < nks)
                #pragma unroll
                for (int mt = 0; mt < 2; ++mt)
                    ldsm_x4(a[ks][mt],
                            hs_base + (rowA + mt * 16) * HS_STRIDE + c * 64 + ks * 32 + colA);
        #pragma unroll
        for (int t = 0; t < 7; ++t) {
            int nt_g = wn + 4 * t;
            if (nt_g < NTILES) {
                uint32_t bb[4];
                ldsm_x4(bb, x_base + (nt_g * 8 + rowB8) * W2S_STRIDE + c * 64 + colB4);
                #pragma unroll
                for (int ks = 0; ks < 2; ++ks)
                    if (ks < nks)
                        #pragma unroll
                        for (int mt = 0; mt < 2; ++mt)
                            mma_fp8(acc[mt][t], a[ks][mt], bb + ks * 2);
            }
        }
    }

    #pragma unroll
    for (int mt = 0; mt < 2; ++mt) {
        #pragma unroll
        for (int half = 0; half < 2; ++half) {
            float sp = 0.f;
            #pragma unroll
            for (int t = 0; t < 7; ++t) {
                int nt_g = wn + 4 * t;
                if (nt_g < NTILES) {
                    int col = nt_g * 8 + 2 * l4;
                    float h0 = fmaxf(acc[mt][t][half * 2 + 0] * INV_HW + b2s[col], 0.f);
                    float h1 = fmaxf(acc[mt][t][half * 2 + 1] * INV_HW + b2s[col + 1], 0.f);
                    sp = fmaf(h0, W3s[col], sp);
                    sp = fmaf(h1, W3s[col + 1], sp);
                }
            }
            sp += __shfl_xor_sync(0xFFFFFFFFu, sp, 1);
            sp += __shfl_xor_sync(0xFFFFFFFFu, sp, 2);
            if (l4 == 0) {
                int r = wm * 32 + mt * 16 + q + 8 * half;
                sred[r][wn] = sp;
            }
        }
    }
    __syncthreads();
    if (tid < MTILE) {
        float s = sred[tid][0] + sred[tid][1] + sred[tid][2] + sred[tid][3] + b3[0];
        int i = bi * 8 + (tid >> 3), j = bj * 8 + (tid & 7);
        if (i > j)
            g_S[((size_t)b * NSEL + i) * NSEL + j] = s;
    }
}

// ---------------- row softmax + fill (block per row) ----------------
__global__ void k_soft(float* __restrict__ out) {
    int bn = blockIdx.x;
    int i = bn % NSEL;
    const float* Srow = g_S + (size_t)bn * NSEL;
    float* orow = out + (size_t)bn * NSEL;
    __shared__ float red[256];
    int tid = threadIdx.x;

    float mx = -1e30f;
    for (int j = tid; j <= i; j += 256) {
        float l = (j == i) ? 0.f : Srow[j];
        mx = fmaxf(mx, l);
    }
    red[tid] = mx; __syncthreads();
    for (int s = 128; s > 0; s >>= 1) {
        if (tid < s) red[tid] = fmaxf(red[tid], red[tid + s]);
        __syncthreads();
    }
    mx = red[0]; __syncthreads();

    float sum = 0.f;
    for (int j = tid; j <= i; j += 256) {
        float l = (j == i) ? 0.f : Srow[j];
        sum += __expf(l - mx);
    }
    red[tid] = sum; __syncthreads();
    for (int s = 128; s > 0; s >>= 1) {
        if (tid < s) red[tid] += red[tid + s];
        __syncthreads();
    }
    sum = red[0];
    float inv = 1.0f / sum;

    for (int j = tid; j < NSEL; j += 256) {
        if (j <= i) {
            float l = (j == i) ? 0.f : Srow[j];
            orow[j] = __expf(l - mx) * inv;
        } else {
            orow[j] = -1000.0f;
        }
    }
}

// ---------------- launch ----------------
extern "C" void kernel_launch(void* const* d_in, const int* in_sizes, int n_in,
                              void* d_out, int out_size) {
    const float* emb = (const float*)d_in[0];
    const int*   idx = (const int*)  d_in[1];
    const float* W1  = (const float*)d_in[2];
    const float* b1  = (const float*)d_in[3];
    const float* W2  = (const float*)d_in[4];
    const float* b2  = (const float*)d_in[5];
    const float* W3  = (const float*)d_in[6];
    const float* b3  = (const float*)d_in[7];
    float* out = (float*)d_out;

    static int configured = 0;
    if (!configured) {
        cudaFuncSetAttribute(k_fused, cudaFuncAttributeMaxDynamicSharedMemorySize,
                             DYN_BYTES);
        cudaFuncSetAttribute(k_abm, cudaFuncAttributeMaxDynamicSharedMemorySize,
                             DYN2_BYTES);
        configured = 1;
    }

    k_prep<<<PREP_BLKS, 256>>>(emb, idx, W1, W2);
    k_abm<<<32, 256, DYN2_BYTES>>>();
    k_fused<<<dim3(NBLK, BATCH), 256, DYN_BYTES>>>(b1, b2, W3, b3);
    k_soft<<<BATCH * NSEL, 256>>>(out);
}